// round 13
// baseline (speedup 1.0000x reference)
#include <cuda_runtime.h>
#include <cuda_fp16.h>

#define PHp 7
#define PWp 7
#define SRs 2
#define SCALEc 0.0625f
#define Bc 2
#define Cc 256
#define Hc 100
#define Wc 152
#define Rc 1024
#define HWc (Hc * Wc)          // 15200 = 95 * 160

// NHWC fp16 scratch: [B][H*W][C] halfs = 15.6 MB
__device__ __align__(16) __half g_nhwc[(size_t)Bc * HWc * Cc];

// ---------------- Phase 1: NCHW fp32 -> NHWC fp16 (unchanged, ~8us) --------
#define TSP 160
#define TPAD 170

__global__ void __launch_bounds__(256) transpose_kernel(const float* __restrict__ in)
{
    __shared__ __half t[64 * TPAD];     // 21,760 B

    int s0 = blockIdx.x * TSP;          // 95 tiles exact
    int c0 = blockIdx.y * 64;           // 4 tiles exact
    int b  = blockIdx.z;
    int tid = threadIdx.x;

    const float* ib = in + ((size_t)b * Cc + c0) * HWc + s0;
    __half* ob = g_nhwc + (size_t)b * HWc * Cc + c0;

    #pragma unroll
    for (int p = 0; p < 10; p++) {
        int idx = p * 256 + tid;
        int j  = idx / 40;
        int c4 = idx - j * 40;
        float4 v = *(const float4*)(ib + (size_t)j * HWc + c4 * 4);
        __half2 h0 = __floats2half2_rn(v.x, v.y);
        __half2 h1 = __floats2half2_rn(v.z, v.w);
        unsigned* w = (unsigned*)(t + j * TPAD + c4 * 4);
        w[0] = *(unsigned*)&h0;
        w[1] = *(unsigned*)&h1;
    }
    __syncthreads();

    int g = tid & 7;
    const __half* tg8 = t + (g * 8) * TPAD;
    #pragma unroll
    for (int p = 0; p < 5; p++) {
        int s = p * 32 + (tid >> 3);
        __half2 p0 = __halves2half2(tg8[0 * TPAD + s], tg8[1 * TPAD + s]);
        __half2 p1 = __halves2half2(tg8[2 * TPAD + s], tg8[3 * TPAD + s]);
        __half2 p2 = __halves2half2(tg8[4 * TPAD + s], tg8[5 * TPAD + s]);
        __half2 p3 = __halves2half2(tg8[6 * TPAD + s], tg8[7 * TPAD + s]);
        uint4 v = make_uint4(*(unsigned*)&p0, *(unsigned*)&p1,
                             *(unsigned*)&p2, *(unsigned*)&p3);
        *(uint4*)(ob + (size_t)(s0 + s) * Cc + g * 8) = v;
    }
}

// ---------------- Phase 2: RoIAlign, one 512-thread block per ROI ----------
//   c8 = tid & 31  -> lane's 8-channel group (32 lanes * 8 = 256 channels)
//   bs = tid >> 5  -> warp id = bin stream (16 streams over 49 bins)
// A warp's corner load = 32 lanes * 16B = 512B contiguous (4 wavefronts).
// Staging: fp16, channel-group stride 394 halfs -> word stride 197 ≡ 5 (mod 32),
// gcd(5,32)=1 -> STS.16 writes are bank-conflict-FREE across the warp.
#define NSS   (PHp * PWp * SRs * SRs)   // 196 subsample records
#define GSTR  394                       // padded stride per 8-ch group (halfs)
#define NBIN  (PHp * PWp)               // 49

__global__ void __launch_bounds__(512) roialign_nhwc_kernel(
    const float* __restrict__ rois,
    float* __restrict__ out)
{
    __shared__ __align__(16) __half s_h[32 * GSTR];   // 25,216 B
    __shared__ int4  ridx[NSS];
    __shared__ uint4 rwgt[NSS];

    int r   = blockIdx.x;
    int tid = threadIdx.x;
    int c8  = tid & 31;
    int bs  = tid >> 5;

    const float* roi = rois + r * 5;
    int b = (int)roi[0];

    if (tid < NSS) {
        float rsw = roi[1] * SCALEc;
        float rsh = roi[2] * SCALEc;
        float roi_w = fmaxf(roi[3] * SCALEc - rsw, 1.0f);
        float roi_h = fmaxf(roi[4] * SCALEc - rsh, 1.0f);
        float bin_h = roi_h * (1.0f / PHp);
        float bin_w = roi_w * (1.0f / PWp);

        int bin = tid >> 2;
        int ss  = tid & 3;
        int ph = bin / PWp, pw = bin - ph * PWp;
        int iy = ss >> 1,  ix = ss & 1;

        float y = rsh + ((float)ph + ((float)iy + 0.5f) * 0.5f) * bin_h;
        float x = rsw + ((float)pw + ((float)ix + 0.5f) * 0.5f) * bin_w;

        bool valid = (y >= -1.0f) && (y <= (float)Hc) &&
                     (x >= -1.0f) && (x <= (float)Wc);

        float yc = fminf(fmaxf(y, 0.0f), (float)(Hc - 1));
        float xc = fminf(fmaxf(x, 0.0f), (float)(Wc - 1));
        int ylo = (int)floorf(yc);
        int xlo = (int)floorf(xc);
        int yhi = min(ylo + 1, Hc - 1);
        int xhi = min(xlo + 1, Wc - 1);
        float ly = yc - (float)ylo;
        float lx = xc - (float)xlo;
        float hy = 1.0f - ly, hx = 1.0f - lx;

        float sc = valid ? 0.25f : 0.0f;
        float w11 = hy * hx * sc, w12 = hy * lx * sc;
        float w21 = ly * hx * sc, w22 = ly * lx * sc;

        ridx[tid] = make_int4((ylo * Wc + xlo) * (Cc * 2),
                              (ylo * Wc + xhi) * (Cc * 2),
                              (yhi * Wc + xlo) * (Cc * 2),
                              (yhi * Wc + xhi) * (Cc * 2));
        __half2 h11 = __floats2half2_rn(w11, w11);
        __half2 h12 = __floats2half2_rn(w12, w12);
        __half2 h21 = __floats2half2_rn(w21, w21);
        __half2 h22 = __floats2half2_rn(w22, w22);
        rwgt[tid] = make_uint4(*(unsigned*)&h11, *(unsigned*)&h12,
                               *(unsigned*)&h21, *(unsigned*)&h22);
    }
    __syncthreads();

    const char* fbb = (const char*)(g_nhwc + (size_t)b * HWc * Cc + c8 * 8);

    for (int bin = bs; bin < NBIN; bin += 16) {
        float a0=0.f,a1=0.f,a2=0.f,a3=0.f,a4=0.f,a5=0.f,a6=0.f,a7=0.f;

        #pragma unroll
        for (int ss = 0; ss < 4; ss++) {
            int4  id = ridx[bin * 4 + ss];
            uint4 wv = rwgt[bin * 4 + ss];

            uint4 u11 = *(const uint4*)(fbb + id.x);
            uint4 u12 = *(const uint4*)(fbb + id.y);
            uint4 u21 = *(const uint4*)(fbb + id.z);
            uint4 u22 = *(const uint4*)(fbb + id.w);

            __half2 w11 = *(__half2*)&wv.x;
            __half2 w12 = *(__half2*)&wv.y;
            __half2 w21 = *(__half2*)&wv.z;
            __half2 w22 = *(__half2*)&wv.w;

            const __half2* c11 = (const __half2*)&u11;
            const __half2* c12 = (const __half2*)&u12;
            const __half2* c21 = (const __half2*)&u21;
            const __half2* c22 = (const __half2*)&u22;

            float2 f;
            #define SUB(J, AA, AB) { \
                __half2 sub = __hfma2(w11, c11[J], __hfma2(w12, c12[J], \
                              __hfma2(w21, c21[J], __hmul2(w22, c22[J])))); \
                f = __half22float2(sub); AA += f.x; AB += f.y; }
            SUB(0, a0, a1)
            SUB(1, a2, a3)
            SUB(2, a4, a5)
            SUB(3, a6, a7)
            #undef SUB
        }

        // conflict-free fp16 staging: group c8 at stride GSTR, channel j at *49
        __half* hp = s_h + c8 * GSTR + bin;
        hp[0 * NBIN] = __float2half_rn(a0);
        hp[1 * NBIN] = __float2half_rn(a1);
        hp[2 * NBIN] = __float2half_rn(a2);
        hp[3 * NBIN] = __float2half_rn(a3);
        hp[4 * NBIN] = __float2half_rn(a4);
        hp[5 * NBIN] = __float2half_rn(a5);
        hp[6 * NBIN] = __float2half_rn(a6);
        hp[7 * NBIN] = __float2half_rn(a7);
    }
    __syncthreads();

    // Copy-out: logical word w = q*196 + rem  ->  staged word q*197 + rem.
    // Each thread handles 2 consecutive logical words -> one float4 store.
    float* ob = out + (size_t)r * (Cc * NBIN);
    const unsigned* sw = (const unsigned*)s_h;
    #pragma unroll 2
    for (int t = tid; t < (Cc * NBIN) / 4; t += 512) {   // 3136 uint2-chunks
        int q    = t / 98;              // 8-channel group
        int rem2 = t - q * 98;          // uint2 index within group (0..97)
        unsigned u0 = sw[q * 197 + 2 * rem2];
        unsigned u1 = sw[q * 197 + 2 * rem2 + 1];
        float2 f0 = __half22float2(*(__half2*)&u0);
        float2 f1 = __half22float2(*(__half2*)&u1);
        *(float4*)(ob + q * 392 + 4 * rem2) = make_float4(f0.x, f0.y, f1.x, f1.y);
    }
}

extern "C" void kernel_launch(void* const* d_in, const int* in_sizes, int n_in,
                              void* d_out, int out_size)
{
    const float* feat = (const float*)d_in[0];
    const float* rois = (const float*)d_in[1];
    float* out = (float*)d_out;

    dim3 tg(HWc / TSP, Cc / 64, Bc);        // 95 x 4 x 2
    transpose_kernel<<<tg, 256>>>(feat);

    roialign_nhwc_kernel<<<Rc, 512>>>(rois, out);
}